// round 7
// baseline (speedup 1.0000x reference)
#include <cuda_runtime.h>
#include <cuda_bf16.h>
#include <math.h>
#include <cstdint>

// ---------------- problem constants ----------------
constexpr int Bn  = 4;
constexpr int C   = 64;      // CIN == COUT
constexpr int H   = 192;
constexpr int Wd  = 192;

// ---------------- tiling ----------------
constexpr int TH   = 16;
constexpr int TW   = 16;
constexpr int WP   = TW + 2;           // 18
constexpr int NPT  = (TH + 2) * WP;    // 324 halo points
constexpr int NB   = 336;              // GEMM N padded to 21 groups of n16
constexpr int NG   = 21;               // n16 groups
constexpr int KPAD = 136;              // Xs/Ws row stride in bf16 (272B, 16B-rotating)
constexpr int NPADQ = 330;             // qkv row stride (floats): 1320B -> 40B rotation
constexpr int BDIM = 512;

// ---------------- smem layout (bytes) ----------------
constexpr int OFF_X    = 0;                          // 336*136*2 = 91392
constexpr int OFF_W    = OFF_X + NB * KPAD * 2;      // 91392
constexpr int OFF_BIAS = OFF_W + 48 * KPAD * 2;      // 104448
constexpr int OFF_QKV  = OFF_BIAS + 256;             // 104704
constexpr int SMEM_TOTAL = OFF_QKV + 48 * NPADQ * 4; // 168064

__device__ __forceinline__ void mma16816(float* c, const uint32_t* a,
                                         uint32_t b0, uint32_t b1) {
    asm volatile(
        "mma.sync.aligned.m16n8k16.row.col.f32.bf16.bf16.f32 "
        "{%0,%1,%2,%3}, {%4,%5,%6,%7}, {%8,%9}, {%0,%1,%2,%3};"
        : "+f"(c[0]), "+f"(c[1]), "+f"(c[2]), "+f"(c[3])
        : "r"(a[0]), "r"(a[1]), "r"(a[2]), "r"(a[3]), "r"(b0), "r"(b1));
}
__device__ __forceinline__ void ldsm_x4(uint32_t* r, uint32_t addr) {
    asm volatile("ldmatrix.sync.aligned.m8n8.x4.shared.b16 {%0,%1,%2,%3}, [%4];"
        : "=r"(r[0]), "=r"(r[1]), "=r"(r[2]), "=r"(r[3]) : "r"(addr));
}
__device__ __forceinline__ uint32_t smem_u32(const void* p) {
    uint32_t a;
    asm("{ .reg .u64 t; cvta.to.shared.u64 t, %1; cvt.u32.u64 %0, t; }" : "=r"(a) : "l"(p));
    return a;
}
__device__ __forceinline__ uint32_t pack_bf16x2(float lo_f, float hi_f) {
    __nv_bfloat162 h = __floats2bfloat162_rn(lo_f, hi_f);
    return *reinterpret_cast<uint32_t*>(&h);
}
__device__ __forceinline__ float fast_ex2(float x) {
    float r;
    asm("ex2.approx.f32 %0, %1;" : "=f"(r) : "f"(x));
    return r;
}
constexpr float LOG2E = 1.4426950408889634f;

__global__ __launch_bounds__(BDIM, 1)
void attn_kernel(const float* __restrict__ x,
                 const float* __restrict__ Wq, const float* __restrict__ bq,
                 const float* __restrict__ Wk, const float* __restrict__ bk,
                 const float* __restrict__ Wv, const float* __restrict__ bv,
                 float* __restrict__ out)
{
    extern __shared__ char smem[];
    __nv_bfloat16* Xs = reinterpret_cast<__nv_bfloat16*>(smem + OFF_X);   // [NB][KPAD] hi|lo
    __nv_bfloat16* Ws = reinterpret_cast<__nv_bfloat16*>(smem + OFF_W);   // [48][KPAD] hi|lo
    float*  bsh = reinterpret_cast<float*>(smem + OFF_BIAS);              // [48]
    float*  qkv = reinterpret_cast<float*>(smem + OFF_QKV);               // [48][NPADQ]

    const int b    = blockIdx.z;
    const int h0   = blockIdx.y * TH;
    const int w0   = blockIdx.x * TW;
    const int tid  = threadIdx.x;
    const int wid  = tid >> 5;
    const int lane = tid & 31;

    // ------------------------------------------------------------------
    // Phase 0: X halo tile -> smem, reflection pad(1), bf16 hi/lo split.
    // Xs row = point, cols [0:64)=Xhi, [64:128)=Xlo.
    // ------------------------------------------------------------------
    const float* xb = x + (size_t)b * C * H * Wd;
    for (int i = tid; i < (C / 2) * NPT; i += BDIM) {
        int cp = i / NPT;
        int p  = i - cp * NPT;
        int c  = cp * 2;
        int py = p / WP;
        int px = p - py * WP;
        int gy = h0 + py - 1;
        gy = (gy < 0) ? -gy : ((gy >= H) ? (2 * H - 2 - gy) : gy);
        int gx = w0 + px - 1;
        gx = (gx < 0) ? -gx : ((gx >= Wd) ? (2 * Wd - 2 - gx) : gx);
        float x0 = xb[(c + 0) * H * Wd + gy * Wd + gx];
        float x1 = xb[(c + 1) * H * Wd + gy * Wd + gx];
        __nv_bfloat16 h0b = __float2bfloat16(x0);
        __nv_bfloat16 h1b = __float2bfloat16(x1);
        float l0 = x0 - __bfloat162float(h0b);
        float l1 = x1 - __bfloat162float(h1b);
        uint32_t hi2 = ((uint32_t)*reinterpret_cast<uint16_t*>(&h0b)) |
                       ((uint32_t)*reinterpret_cast<uint16_t*>(&h1b) << 16);
        uint32_t lo2 = pack_bf16x2(l0, l1);
        uint32_t* row = reinterpret_cast<uint32_t*>(Xs + p * KPAD);
        row[c / 2]      = hi2;
        row[32 + c / 2] = lo2;
    }
    // zero pad rows 324..335 (cols 0..127)
    for (int i = tid; i < (NB - NPT) * 64; i += BDIM) {
        int p  = NPT + i / 64;
        int c2 = i % 64;
        reinterpret_cast<uint32_t*>(Xs + p * KPAD)[c2] = 0u;
    }

    // softmax assignment: thread -> pixel pair (even tx) x 4 channels
    const int pid  = tid & 127;
    const int cg4  = tid >> 7;          // channel group 0..3
    const int spy  = pid >> 3;          // 0..15
    const int stx  = (pid & 7) * 2;     // even tx of pixel pair
    float* outbase = out + ((size_t)b * C) * H * Wd + (size_t)(h0 + spy) * Wd + (w0 + stx);

    // GEMM warp assignment: 12 warps own n16-groups over all 48 m rows
    const bool gemm_w = (wid < 12);
    const int g0 = wid;                 // group 1
    const int g1 = wid + 12;            // group 2 (valid if < NG)
    const bool has2 = (g1 < NG);

    const int lrow = (lane & 7) + ((lane >> 3) & 1) * 8;
    const int lkof = (lane >> 4) * 8;
    const uint32_t xs_base = smem_u32(Xs);
    const uint32_t ws_base = smem_u32(Ws);

    // ------------------------------------------------------------------
    // chunk loop: 4 chunks of 16 channels. rows: [q16 | k16 | v16]
    // ------------------------------------------------------------------
    for (int ck = 0; ck < 4; ++ck) {
        const int c0 = ck * 16;

        // Phase A: chunk weights -> Ws [hi|lo], bias -> bsh
        for (int i = tid; i < 48 * 32; i += BDIM) {
            int m  = i >> 5;
            int cp = i & 31;
            int c  = cp * 2;
            int mat = m >> 4;
            int ch  = c0 + (m & 15);
            const float* Wsrc = (mat == 0) ? Wq : (mat == 1) ? Wk : Wv;
            float2 w = *reinterpret_cast<const float2*>(Wsrc + ch * C + c);
            __nv_bfloat16 h0b = __float2bfloat16(w.x);
            __nv_bfloat16 h1b = __float2bfloat16(w.y);
            float l0 = w.x - __bfloat162float(h0b);
            float l1 = w.y - __bfloat162float(h1b);
            uint32_t hi2 = ((uint32_t)*reinterpret_cast<uint16_t*>(&h0b)) |
                           ((uint32_t)*reinterpret_cast<uint16_t*>(&h1b) << 16);
            uint32_t lo2 = pack_bf16x2(l0, l1);
            uint32_t* row = reinterpret_cast<uint32_t*>(Ws + m * KPAD);
            row[c / 2]      = hi2;
            row[32 + c / 2] = lo2;
        }
        if (tid < 48) {
            int mat = tid >> 4;
            int ch  = c0 + (tid & 15);
            bsh[tid] = ((mat == 0) ? bq : (mat == 1) ? bk : bv)[ch];
        }
        __syncthreads();   // Ws/bias visible; prev softmax done -> qkv reusable

        // Phase B: HMMA GEMM qkv[48][336] = W'[48][192] * X'[192][336]
        // 3-term fp32 emulation by k-offset re-indexing:
        //   s0-3: Whi*Xhi   s4-7: Wlo*Xhi   s8-11: Whi*Xlo
        if (gemm_w) {
            float acc[2][3][2][4];    // [group][mtile][n8][4]
            #pragma unroll
            for (int mt = 0; mt < 3; ++mt) {
                float b0v = bsh[mt * 16 + (lane >> 2)];
                float b1v = bsh[mt * 16 + (lane >> 2) + 8];
                #pragma unroll
                for (int gi = 0; gi < 2; ++gi)
                    #pragma unroll
                    for (int nc = 0; nc < 2; ++nc) {
                        acc[gi][mt][nc][0] = b0v; acc[gi][mt][nc][1] = b0v;
                        acc[gi][mt][nc][2] = b1v; acc[gi][mt][nc][3] = b1v;
                    }
            }
            #pragma unroll
            for (int s = 0; s < 12; ++s) {
                const int ak = (s < 4) ? s * 16 : (s < 8) ? 64 + (s - 4) * 16 : (s - 8) * 16;
                const int bk = (s < 4) ? s * 16 : (s < 8) ? (s - 4) * 16 : 64 + (s - 8) * 16;
                uint32_t a[3][4];
                #pragma unroll
                for (int mt = 0; mt < 3; ++mt)
                    ldsm_x4(a[mt], ws_base +
                        (uint32_t)((mt * 16 + lrow) * (KPAD * 2) + (ak + lkof) * 2));
                uint32_t br[4];
                ldsm_x4(br, xs_base +
                    (uint32_t)((g0 * 16 + lrow) * (KPAD * 2) + (bk + lkof) * 2));
                #pragma unroll
                for (int mt = 0; mt < 3; ++mt) {
                    mma16816(acc[0][mt][0], a[mt], br[0], br[2]);
                    mma16816(acc[0][mt][1], a[mt], br[1], br[3]);
                }
                if (has2) {
                    uint32_t b2[4];
                    ldsm_x4(b2, xs_base +
                        (uint32_t)((g1 * 16 + lrow) * (KPAD * 2) + (bk + lkof) * 2));
                    #pragma unroll
                    for (int mt = 0; mt < 3; ++mt) {
                        mma16816(acc[1][mt][0], a[mt], b2[0], b2[2]);
                        mma16816(acc[1][mt][1], a[mt], b2[1], b2[3]);
                    }
                }
            }
            // store D -> qkv (skip padded cols >= 328)
            #pragma unroll
            for (int gi = 0; gi < 2; ++gi) {
                const int g = (gi == 0) ? g0 : g1;
                if (gi == 1 && !has2) break;
                const int col0 = g * 16 + (lane & 3) * 2;
                #pragma unroll
                for (int mt = 0; mt < 3; ++mt) {
                    const int r0 = mt * 16 + (lane >> 2);
                    *reinterpret_cast<float2*>(qkv + r0 * NPADQ + col0) =
                        make_float2(acc[gi][mt][0][0], acc[gi][mt][0][1]);
                    *reinterpret_cast<float2*>(qkv + (r0 + 8) * NPADQ + col0) =
                        make_float2(acc[gi][mt][0][2], acc[gi][mt][0][3]);
                    if (g < NG - 1) {
                        *reinterpret_cast<float2*>(qkv + r0 * NPADQ + col0 + 8) =
                            make_float2(acc[gi][mt][1][0], acc[gi][mt][1][1]);
                        *reinterpret_cast<float2*>(qkv + (r0 + 8) * NPADQ + col0 + 8) =
                            make_float2(acc[gi][mt][1][2], acc[gi][mt][1][3]);
                    }
                }
            }
        }
        __syncthreads();   // qkv ready

        // Phase C: softmax, 2 adjacent pixels x 4 channels per thread
        #pragma unroll 1
        for (int r = 0; r < 4; ++r) {
            const int ch = cg4 * 4 + r;
            const float* qr = qkv + ch * NPADQ;
            const float* kr = qkv + (16 + ch) * NPADQ;
            const float* vr = qkv + (32 + ch) * NPADQ;
            const int ip0 = (spy + 1) * WP + stx + 1;
            const float q0 = qr[ip0]     * LOG2E;
            const float q1 = qr[ip0 + 1] * LOG2E;
            float s0 = 0.f, a0 = 0.f, s1 = 0.f, a1 = 0.f;
            #pragma unroll
            for (int rr = 0; rr < 3; ++rr) {
                const int off = (spy + rr) * WP + stx;
                float2 ka = *reinterpret_cast<const float2*>(kr + off);
                float2 kb = *reinterpret_cast<const float2*>(kr + off + 2);
                float2 va = *reinterpret_cast<const float2*>(vr + off);
                float2 vb = *reinterpret_cast<const float2*>(vr + off + 2);
                float e;
                e = fast_ex2(q0 * ka.x); s0 += e; a0 = fmaf(e, va.x, a0);
                e = fast_ex2(q0 * ka.y); s0 += e; a0 = fmaf(e, va.y, a0);
                e = fast_ex2(q0 * kb.x); s0 += e; a0 = fmaf(e, vb.x, a0);
                e = fast_ex2(q1 * ka.y); s1 += e; a1 = fmaf(e, va.y, a1);
                e = fast_ex2(q1 * kb.x); s1 += e; a1 = fmaf(e, vb.x, a1);
                e = fast_ex2(q1 * kb.y); s1 += e; a1 = fmaf(e, vb.y, a1);
            }
            *reinterpret_cast<float2*>(outbase + (size_t)(c0 + ch) * H * Wd) =
                make_float2(__fdividef(a0, s0), __fdividef(a1, s1));
        }
        // next iteration's post-A __syncthreads orders qkv reuse
    }
}

extern "C" void kernel_launch(void* const* d_in, const int* in_sizes, int n_in,
                              void* d_out, int out_size)
{
    const float* x  = (const float*)d_in[0];
    const float* Wq = (const float*)d_in[1];
    const float* bq = (const float*)d_in[2];
    const float* Wk = (const float*)d_in[3];
    const float* bk = (const float*)d_in[4];
    const float* Wv = (const float*)d_in[5];
    const float* bv = (const float*)d_in[6];
    float* out = (float*)d_out;

    cudaFuncSetAttribute(attn_kernel, cudaFuncAttributeMaxDynamicSharedMemorySize,
                         SMEM_TOTAL);
    dim3 grid(Wd / TW, H / TH, Bn);   // (12, 12, 4)
    attn_kernel<<<grid, BDIM, SMEM_TOTAL>>>(x, Wq, bq, Wk, bk, Wv, bv, out);
}